// round 14
// baseline (speedup 1.0000x reference)
#include <cuda_runtime.h>
#include <cuda_bf16.h>
#include <cuda_fp16.h>
#include <cstdint>

#define BB 4
#define SS 4096
#define HH 1024
#define DD 64

// fp16 projection outputs. K is pre-scaled by 0.125*log2(e) so the
// attention kernel computes p = exp2(K.Q) with a single MUFU.
__device__ __align__(16) __half g_Kh[BB * SS * DD];
__device__ __align__(16) __half g_Qh[BB * SS * DD];
__device__ __align__(16) __half g_VTh[BB * DD * SS];   // transposed [b][d][t]

// ===========================================================================
// Helpers
// ===========================================================================
__device__ __forceinline__ uint32_t smem_u32_of(const void* p) {
    uint32_t addr;
    asm("{ .reg .u64 tmp; cvta.to.shared.u64 tmp, %1; cvt.u32.u64 %0, tmp; }"
        : "=r"(addr) : "l"(p));
    return addr;
}

__device__ __forceinline__ void ldsm_x4(uint32_t* r, uint32_t addr) {
    asm volatile("ldmatrix.sync.aligned.m8n8.x4.shared.b16 {%0,%1,%2,%3}, [%4];"
                 : "=r"(r[0]), "=r"(r[1]), "=r"(r[2]), "=r"(r[3]) : "r"(addr));
}
__device__ __forceinline__ void mma16816h(float* d, const uint32_t* a,
                                          const uint32_t* b) {
    asm volatile(
        "mma.sync.aligned.m16n8k16.row.col.f32.f16.f16.f32 "
        "{%0,%1,%2,%3}, {%4,%5,%6,%7}, {%8,%9}, {%0,%1,%2,%3};"
        : "+f"(d[0]), "+f"(d[1]), "+f"(d[2]), "+f"(d[3])
        : "r"(a[0]), "r"(a[1]), "r"(a[2]), "r"(a[3]), "r"(b[0]), "r"(b[1]));
}

__device__ __forceinline__ uint32_t pack_h2(float lo, float hi) {
    __half2 t = __floats2half2_rn(lo, hi);
    return *(uint32_t*)&t;
}

__device__ __forceinline__ void cp_async16(uint32_t smem_addr, const void* gptr) {
    asm volatile("cp.async.ca.shared.global [%0], [%1], 16;"
                 :: "r"(smem_addr), "l"(gptr) : "memory");
}
#define CP_COMMIT() asm volatile("cp.async.commit_group;" ::: "memory")
#define CP_WAIT(n)  asm volatile("cp.async.wait_group %0;" :: "n"(n) : "memory")

__device__ __forceinline__ uint32_t a_addr_ld(uint32_t base, int row0, int col0,
                                              int lane, int ld) {
    int t = lane >> 3, ri = lane & 7;
    int row = row0 + ri + ((t & 1) << 3);
    int col = col0 + ((t >> 1) << 3);
    return base + (uint32_t)(row * ld + col) * 2;
}
__device__ __forceinline__ uint32_t b2_addr_ld(uint32_t base, int n0, int k0,
                                               int lane, int ld) {
    int row = n0 + ((lane >> 4) << 3) + (lane & 7);
    int col = k0 + (((lane >> 3) & 1) << 3);
    return base + (uint32_t)(row * ld + col) * 2;
}

// ===========================================================================
// Projection R14: single-pass fp16, DOUBLE-BUFFERED smem tiles, one
// __syncthreads per BK=32 iteration. K scaled by 0.125*log2e.
// ===========================================================================
#define PLDP 40
#define PBUF_B 25600                        // X (10240) + W (15360)
#define PXO 0
#define PWO 10240
#define PSMEM (2 * PBUF_B)                  // 51200

__global__ void __launch_bounds__(256) proj_mma_kernel(const float* __restrict__ x,
                                                       const float* __restrict__ Wk,
                                                       const float* __restrict__ Wq,
                                                       const float* __restrict__ Wv) {
    extern __shared__ char smem[];
    const uint32_t sb = smem_u32_of(smem);

    const int tid = threadIdx.x;
    const int wid = tid >> 5;
    const int lane = tid & 31;
    const int warp_m = wid & 3;
    const int warp_n = wid >> 2;
    const int m0 = blockIdx.x * 128;

    float4 xr[4], wr[6];

    // iter-0 slab -> regs -> buf0
#pragma unroll
    for (int j = 0; j < 4; j++) {
        int idx = tid + 256 * j;
        xr[j] = *(const float4*)&x[(size_t)(m0 + (idx >> 3)) * HH + (idx & 7) * 4];
    }
#pragma unroll
    for (int j = 0; j < 6; j++) {
        int idx = tid + 256 * j;
        int row = idx >> 3;
        const float* W = (row < 64) ? Wk : ((row < 128) ? Wq : Wv);
        wr[j] = *(const float4*)&W[(size_t)(row & 63) * HH + (idx & 7) * 4];
    }
#pragma unroll
    for (int j = 0; j < 4; j++) {
        int idx = tid + 256 * j;
        int row = idx >> 3, c4 = idx & 7;
        *(uint2*)(smem + PXO + row * PLDP * 2 + c4 * 8) =
            make_uint2(pack_h2(xr[j].x, xr[j].y), pack_h2(xr[j].z, xr[j].w));
    }
#pragma unroll
    for (int j = 0; j < 6; j++) {
        int idx = tid + 256 * j;
        int row = idx >> 3, c4 = idx & 7;
        *(uint2*)(smem + PWO + row * PLDP * 2 + c4 * 8) =
            make_uint2(pack_h2(wr[j].x, wr[j].y), pack_h2(wr[j].z, wr[j].w));
    }

    float acc[2][12][4];
#pragma unroll
    for (int mt = 0; mt < 2; mt++)
#pragma unroll
        for (int nn = 0; nn < 12; nn++)
#pragma unroll
            for (int e = 0; e < 4; e++) acc[mt][nn][e] = 0.0f;

#pragma unroll 1
    for (int it = 0; it < 32; it++) {
        // Publishes buf[it&1]; also proves all warps finished reading
        // buf[(it+1)&1] last iteration -> the STS below is WAR-safe.
        __syncthreads();

        const uint32_t cbuf = sb + (uint32_t)(it & 1) * PBUF_B;

        // prefetch next slab (overlaps MMA)
        if (it + 1 < 32) {
            int k0 = (it + 1) * 32;
#pragma unroll
            for (int j = 0; j < 4; j++) {
                int idx = tid + 256 * j;
                xr[j] = *(const float4*)&x[(size_t)(m0 + (idx >> 3)) * HH + k0 + (idx & 7) * 4];
            }
#pragma unroll
            for (int j = 0; j < 6; j++) {
                int idx = tid + 256 * j;
                int row = idx >> 3;
                const float* W = (row < 64) ? Wk : ((row < 128) ? Wq : Wv);
                wr[j] = *(const float4*)&W[(size_t)(row & 63) * HH + k0 + (idx & 7) * 4];
            }
        }

        // MMA on current buffer
#pragma unroll
        for (int kc = 0; kc < 2; kc++) {
            uint32_t ah[2][4];
#pragma unroll
            for (int mt = 0; mt < 2; mt++)
                ldsm_x4(ah[mt], a_addr_ld(cbuf + PXO, warp_m * 32 + mt * 16, kc * 16, lane, PLDP));
#pragma unroll
            for (int nh = 0; nh < 2; nh++) {
                uint32_t bh[6][2];
#pragma unroll
                for (int pp = 0; pp < 3; pp++) {
                    uint32_t tmp[4];
                    int n0 = warp_n * 96 + nh * 48 + pp * 16;
                    ldsm_x4(tmp, b2_addr_ld(cbuf + PWO, n0, kc * 16, lane, PLDP));
                    bh[2 * pp][0] = tmp[0]; bh[2 * pp][1] = tmp[1];
                    bh[2 * pp + 1][0] = tmp[2]; bh[2 * pp + 1][1] = tmp[3];
                }
#pragma unroll
                for (int mt = 0; mt < 2; mt++)
#pragma unroll
                    for (int nt = 0; nt < 6; nt++)
                        mma16816h(acc[mt][nh * 6 + nt], ah[mt], bh[nt]);
            }
        }

        // stage next slab into the other buffer (generic pointers!)
        if (it + 1 < 32) {
            char* nb = smem + (size_t)((it + 1) & 1) * PBUF_B;
#pragma unroll
            for (int j = 0; j < 4; j++) {
                int idx = tid + 256 * j;
                int row = idx >> 3, c4 = idx & 7;
                *(uint2*)(nb + PXO + row * PLDP * 2 + c4 * 8) =
                    make_uint2(pack_h2(xr[j].x, xr[j].y), pack_h2(xr[j].z, xr[j].w));
            }
#pragma unroll
            for (int j = 0; j < 6; j++) {
                int idx = tid + 256 * j;
                int row = idx >> 3, c4 = idx & 7;
                *(uint2*)(nb + PWO + row * PLDP * 2 + c4 * 8) =
                    make_uint2(pack_h2(wr[j].x, wr[j].y), pack_h2(wr[j].z, wr[j].w));
            }
        }
    }

    // ---- epilogue ----
    const float KSC = 0.125f * 1.44269504f;   // softmax scale + log2(e)
#pragma unroll
    for (int mt = 0; mt < 2; mt++)
#pragma unroll
        for (int rp = 0; rp < 2; rp++) {
            int row = m0 + warp_m * 32 + mt * 16 + rp * 8 + (lane >> 2);
            int bb_ = row >> 12, t = row & 4095;
#pragma unroll
            for (int nn = 0; nn < 12; nn++) {
                int n = warp_n * 96 + nn * 8 + (lane & 3) * 2;
                int which = n >> 6, d = n & 63;
                float v0 = acc[mt][nn][rp * 2 + 0];
                float v1 = acc[mt][nn][rp * 2 + 1];
                if (which == 2) {
                    size_t base = (size_t)bb_ * DD * SS;
                    g_VTh[base + (size_t)d * SS + t] = __float2half(v0);
                    g_VTh[base + (size_t)(d + 1) * SS + t] = __float2half(v1);
                } else if (which == 1) {
                    *(uint32_t*)&g_Qh[(size_t)row * DD + d] = pack_h2(v0, v1);
                } else {
                    *(uint32_t*)&g_Kh[(size_t)row * DD + d] =
                        pack_h2(v0 * KSC, v1 * KSC);
                }
            }
        }
}

// ===========================================================================
// Attention (unchanged from R12 — 57.5us): 128-t double-buffered steps,
// two 64-t sub-chunks per barrier, exp2 softmax, 2x2 warp grid.
// ===========================================================================
#define LDP 72
#define LDP2 136
#define QT_B (128 * LDP * 2)
#define VT_B (64 * LDP2 * 2)
#define BUF2_B (QT_B + VT_B)
#define AMSK (2 * BUF2_B)
#define ASMEM (AMSK + SS * 4)

__global__ void __launch_bounds__(128, 2) attn_mma_kernel(const int* __restrict__ mask,
                                                          float* __restrict__ out) {
    extern __shared__ char smem[];
    const uint32_t sb = smem_u32_of(smem);

    const int tid = threadIdx.x;
    const int wid = tid >> 5;
    const int lane = tid & 31;
    const int gid = lane >> 2;
    const int tig = lane & 3;
    const int warp_m = wid & 1;
    const int warp_n = wid >> 1;
    const int b = blockIdx.y;
    const int r0 = blockIdx.x * 64;

    const __half* Kh = g_Kh + (size_t)b * SS * DD;
    const __half* Qh = g_Qh + (size_t)b * SS * DD;
    const __half* VTh = g_VTh + (size_t)b * DD * SS;

    float* msk = (float*)(smem + AMSK);

#pragma unroll
    for (int j = 0; j < 4; j++) {
        int chunk = tid + 128 * j;
        int row = chunk >> 3, c8 = chunk & 7;
        cp_async16(sb + (uint32_t)(row * 144 + c8 * 16),
                   Kh + (size_t)(r0 + row) * DD + c8 * 8);
    }
#pragma unroll
    for (int j = 0; j < 8; j++) {
        int chunk = tid + 128 * j;
        cp_async16(sb + AMSK + chunk * 16, mask + b * SS + chunk * 4);
    }
    CP_COMMIT();
    CP_WAIT(0);
    __syncthreads();

    uint32_t Kf[2][4][4];
#pragma unroll
    for (int mi = 0; mi < 2; mi++)
#pragma unroll
        for (int kc = 0; kc < 4; kc++)
            ldsm_x4(Kf[mi][kc],
                    a_addr_ld(sb, warp_m * 32 + mi * 16, kc * 16, lane, LDP));

#pragma unroll
    for (int j = 0; j < 32; j++) {
        int idx = tid + 128 * j;
        msk[idx] = (float)((int*)msk)[idx];
    }
    __syncthreads();

#pragma unroll
    for (int j = 0; j < 8; j++) {
        int chunk = tid + 128 * j;
        int row = chunk >> 3, c8 = chunk & 7;
        cp_async16(sb + (uint32_t)(row * 144 + c8 * 16),
                   Qh + (size_t)row * DD + c8 * 8);
    }
#pragma unroll
    for (int j = 0; j < 8; j++) {
        int chunk = tid + 128 * j;
        int row = chunk >> 4, c16 = chunk & 15;
        cp_async16(sb + QT_B + (uint32_t)(row * 272 + c16 * 16),
                   VTh + (size_t)row * SS + c16 * 8);
    }
    CP_COMMIT();

    float oacc[2][8][4];
#pragma unroll
    for (int mi = 0; mi < 2; mi++)
#pragma unroll
        for (int nt = 0; nt < 8; nt++)
#pragma unroll
            for (int e = 0; e < 4; e++) oacc[mi][nt][e] = 0.0f;
    float l_part[4] = {0.0f, 0.0f, 0.0f, 0.0f};

    auto do_sub = [&](uint32_t Qb, uint32_t Vb, int tb, int mglob) {
        float sacc[2][4][4];
#pragma unroll
        for (int mi = 0; mi < 2; mi++)
#pragma unroll
            for (int nj = 0; nj < 4; nj++)
#pragma unroll
                for (int e = 0; e < 4; e++) sacc[mi][nj][e] = 0.0f;

#pragma unroll
        for (int kc = 0; kc < 4; kc++) {
#pragma unroll
            for (int nb = 0; nb < 2; nb++) {
                uint32_t bq[4];
                ldsm_x4(bq, b2_addr_ld(Qb, tb + nb * 16, kc * 16, lane, LDP));
#pragma unroll
                for (int mi = 0; mi < 2; mi++) {
                    mma16816h(sacc[mi][nb * 2 + 0], Kf[mi][kc], bq + 0);
                    mma16816h(sacc[mi][nb * 2 + 1], Kf[mi][kc], bq + 2);
                }
            }
        }

#pragma unroll
        for (int nj = 0; nj < 4; nj++) {
            float mf0 = msk[mglob + nj * 8 + tig * 2 + 0];
            float mf1 = msk[mglob + nj * 8 + tig * 2 + 1];
#pragma unroll
            for (int mi = 0; mi < 2; mi++) {
                float p0 = mf0 * exp2f(sacc[mi][nj][0]);
                float p1 = mf1 * exp2f(sacc[mi][nj][1]);
                float p2 = mf0 * exp2f(sacc[mi][nj][2]);
                float p3 = mf1 * exp2f(sacc[mi][nj][3]);
                sacc[mi][nj][0] = p0; sacc[mi][nj][1] = p1;
                sacc[mi][nj][2] = p2; sacc[mi][nj][3] = p3;
                l_part[mi * 2 + 0] += p0 + p1;
                l_part[mi * 2 + 1] += p2 + p3;
            }
        }

        uint32_t Pf[2][2][4];
#pragma unroll
        for (int mi = 0; mi < 2; mi++)
#pragma unroll
            for (int kt = 0; kt < 2; kt++) {
                int t0 = 2 * kt, t1 = 2 * kt + 1;
                Pf[mi][kt][0] = pack_h2(sacc[mi][t0][0], sacc[mi][t0][1]);
                Pf[mi][kt][1] = pack_h2(sacc[mi][t0][2], sacc[mi][t0][3]);
                Pf[mi][kt][2] = pack_h2(sacc[mi][t1][0], sacc[mi][t1][1]);
                Pf[mi][kt][3] = pack_h2(sacc[mi][t1][2], sacc[mi][t1][3]);
            }

#pragma unroll
        for (int kt = 0; kt < 2; kt++) {
#pragma unroll
            for (int p = 0; p < 4; p++) {
                uint32_t bv[4];
                ldsm_x4(bv, b2_addr_ld(Vb, p * 16, tb + kt * 16, lane, LDP2));
#pragma unroll
                for (int mi = 0; mi < 2; mi++) {
                    mma16816h(oacc[mi][2 * p + 0], Pf[mi][kt], bv + 0);
                    mma16816h(oacc[mi][2 * p + 1], Pf[mi][kt], bv + 2);
                }
            }
        }
    };

#pragma unroll 1
    for (int step = 0; step < 32; step++) {
        CP_WAIT(0);
        __syncthreads();

        if (step + 1 < 32) {
            int t0n = (step + 1) * 128;
            uint32_t bufn = sb + (uint32_t)((step + 1) & 1) * BUF2_B;
#pragma unroll
            for (int j = 0; j < 8; j++) {
                int chunk = tid + 128 * j;
                int row = chunk >> 3, c8 = chunk & 7;
                cp_async16(bufn + (uint32_t)(row * 144 + c8 * 16),
                           Qh + (size_t)(t0n + row) * DD + c8 * 8);
            }
#pragma unroll
            for (int j = 0; j < 8; j++) {
                int chunk = tid + 128 * j;
                int row = chunk >> 4, c16 = chunk & 15;
                cp_async16(bufn + QT_B + (uint32_t)(row * 272 + c16 * 16),
                           VTh + (size_t)row * SS + t0n + c16 * 8);
            }
            CP_COMMIT();
        }

        uint32_t buf = sb + (uint32_t)(step & 1) * BUF2_B;
        uint32_t Qb = buf, Vb = buf + QT_B;
        int mg = step * 128 + warp_n * 32;

        do_sub(Qb, Vb, warp_n * 32, mg);
        do_sub(Qb, Vb, 64 + warp_n * 32, mg + 64);
    }

    // ---- epilogue ----
#pragma unroll
    for (int i = 0; i < 4; i++) {
        l_part[i] += __shfl_xor_sync(0xffffffffu, l_part[i], 1);
        l_part[i] += __shfl_xor_sync(0xffffffffu, l_part[i], 2);
    }

    float* Osh = (float*)smem;
    float* l_sh = (float*)(smem + 16896);
    __syncthreads();

    if (warp_n == 1) {
#pragma unroll
        for (int mi = 0; mi < 2; mi++)
#pragma unroll
            for (int rp = 0; rp < 2; rp++) {
                int r = warp_m * 32 + mi * 16 + rp * 8 + gid;
#pragma unroll
                for (int nj = 0; nj < 8; nj++) {
                    Osh[r * 66 + nj * 8 + tig * 2 + 0] = oacc[mi][nj][rp * 2 + 0];
                    Osh[r * 66 + nj * 8 + tig * 2 + 1] = oacc[mi][nj][rp * 2 + 1];
                }
                if (tig == 0) l_sh[r] = l_part[mi * 2 + rp];
            }
    }
    __syncthreads();

    if (warp_n == 0) {
#pragma unroll
        for (int mi = 0; mi < 2; mi++)
#pragma unroll
            for (int rp = 0; rp < 2; rp++) {
                int r = warp_m * 32 + mi * 16 + rp * 8 + gid;
                float inv = 1.0f / (l_part[mi * 2 + rp] + l_sh[r]);
#pragma unroll
                for (int nj = 0; nj < 8; nj++) {
                    float o0 = oacc[mi][nj][rp * 2 + 0] + Osh[r * 66 + nj * 8 + tig * 2 + 0];
                    float o1 = oacc[mi][nj][rp * 2 + 1] + Osh[r * 66 + nj * 8 + tig * 2 + 1];
                    *(float2*)&out[((size_t)b * SS + r0 + r) * DD + nj * 8 + tig * 2] =
                        make_float2(o0 * inv, o1 * inv);
                }
            }
    }
}

extern "C" void kernel_launch(void* const* d_in, const int* in_sizes, int n_in,
                              void* d_out, int out_size) {
    const float* x    = (const float*)d_in[0];
    const int*   mask = (const int*)d_in[1];
    const float* Wk   = (const float*)d_in[2];
    const float* Wq   = (const float*)d_in[3];
    const float* Wv   = (const float*)d_in[4];
    float* out = (float*)d_out;

    cudaFuncSetAttribute(proj_mma_kernel,
                         cudaFuncAttributeMaxDynamicSharedMemorySize, PSMEM);
    proj_mma_kernel<<<128, 256, PSMEM>>>(x, Wk, Wq, Wv);

    cudaFuncSetAttribute(attn_mma_kernel,
                         cudaFuncAttributeMaxDynamicSharedMemorySize, ASMEM);
    dim3 grid(64, 4);
    attn_mma_kernel<<<grid, 128, ASMEM>>>(mask, out);
}